// round 12
// baseline (speedup 1.0000x reference)
#include <cuda_runtime.h>
#include <cuda_fp16.h>
#include <cstdint>

// ---------------------------------------------------------------------------
// MalConv via single-pass fp16 mma.sync (m16n8k16, f32 accumulate).
//   C[16000,256] = E[16000,4000] x W[4000,256], fp16 operands, fp32 accum.
//   Columns interleaved (g1_j, g2_j) so mma C-pairs = (g1, g2).
//   CTA: 64 patches x 64 cols, 4 warps (2m x 2n), warp tile 32x32.
//   Grid: 250 m-tiles x 4 n-tiles = 1000 (fine tiles -> SM load balance).
//   K: 63 chunks of 64. 3-stage cp.async ring, one __syncthreads per chunk.
// ---------------------------------------------------------------------------

#define NCHUNK   63
#define BATCH    8

// stage layout: A 64p x 128B (8 KB) | B 64n x 128B (8 KB)
#define A_OFF    0
#define B_OFF    8192
#define STG      16384
// after 3 stages:
#define EMB_OFF  49152          // uint4[257] fp16x8 rows
#define SMEM_TOTAL 53264

__device__ __align__(16) unsigned char g_B[NCHUNK * 32768]; // [c][256n][128B]
__device__ int g_m[BATCH * 128];

// ---------------------------------------------------------------------------
// pack: one block per interleaved column n (256 blocks). Coalesced W row
// staging in smem; swizzled fp16 writes. Block 0 also zeroes g_m.
__global__ void pack_kernel(const float* __restrict__ W1,
                            const float* __restrict__ W2) {
    __shared__ float sw[4000];
    const int n   = blockIdx.x;              // 0..255
    const int tid = threadIdx.x;
    const int j   = n >> 1;
    const float* Wsrc = (n & 1) ? W2 : W1;
    if (n == 0) {
        for (int i = tid; i < BATCH * 128; i += 256) g_m[i] = 0;
    }
    for (int i = tid; i < 4000; i += 256) sw[i] = Wsrc[j * 4000 + i];
    __syncthreads();
    for (int idx = tid; idx < NCHUNK * 64; idx += 256) {
        int c  = idx >> 6;
        int kk = idx & 63;
        int K  = c * 64 + kk;
        int k  = K >> 3, ch = K & 7;
        float v = (k < 500) ? sw[ch * 500 + k] : 0.f;
        int quad = kk >> 3;
        size_t addr = (size_t)c * 32768 + n * 128
                    + (((quad ^ (n & 7)) << 4) | ((kk & 7) * 2));
        *(__half*)(g_B + addr) = __float2half(v);
    }
}

// ---------------------------------------------------------------------------
__device__ __forceinline__ void cp_async16(uint32_t dst, const void* src) {
    asm volatile("cp.async.cg.shared.global [%0], [%1], 16;" :: "r"(dst), "l"(src));
}
__device__ __forceinline__ void cp_commit() { asm volatile("cp.async.commit_group;"); }
template <int N> __device__ __forceinline__ void cp_wait() {
    asm volatile("cp.async.wait_group %0;" :: "n"(N));
}
__device__ __forceinline__ void ldsm4(uint32_t a, uint32_t* r) {
    asm volatile("ldmatrix.sync.aligned.m8n8.x4.shared.b16 {%0,%1,%2,%3}, [%4];"
                 : "=r"(r[0]), "=r"(r[1]), "=r"(r[2]), "=r"(r[3]) : "r"(a));
}
__device__ __forceinline__ void mma16816(float* d, const uint32_t* a,
                                         uint32_t b0, uint32_t b1) {
    asm volatile(
        "mma.sync.aligned.m16n8k16.row.col.f32.f16.f16.f32 "
        "{%0,%1,%2,%3}, {%4,%5,%6,%7}, {%8,%9}, {%0,%1,%2,%3};"
        : "+f"(d[0]), "+f"(d[1]), "+f"(d[2]), "+f"(d[3])
        : "r"(a[0]), "r"(a[1]), "r"(a[2]), "r"(a[3]), "r"(b0), "r"(b1));
}
__device__ __forceinline__ uint32_t swz128(int row, int quad) {
    return row * 128 + (((quad ^ (row & 7)) << 4));
}

// ---------------------------------------------------------------------------
__global__ void __launch_bounds__(128, 4)
malconv_kernel(const int* __restrict__ x, const float* __restrict__ emb,
               const float* __restrict__ b1, const float* __restrict__ b2) {
    extern __shared__ __align__(16) char smem[];
    const uint32_t sb = (uint32_t)__cvta_generic_to_shared(smem);
    const int tid  = threadIdx.x;
    const int lane = tid & 31;
    const int wid  = tid >> 5;          // 0..3
    const int wm   = wid >> 1;          // 0..1  (m-warp)
    const int wn   = wid & 1;           // 0..1  (n-warp)
    const int mt   = blockIdx.x >> 2;   // 0..249
    const int nt   = blockIdx.x & 3;    // 0..3

    // fp16 embedding table: uint4[257] (8 channels = 16 B per row)
    uint4* eT = (uint4*)(smem + EMB_OFF);
    for (int i = tid; i < 257 * 8; i += 128)
        ((__half*)eT)[i] = __float2half(emb[i]);

    float acc[2][4][4];
#pragma unroll
    for (int a = 0; a < 2; a++)
#pragma unroll
        for (int b = 0; b < 4; b++)
#pragma unroll
            for (int q = 0; q < 4; q++) acc[a][b][q] = 0.f;

    // builder: 2 threads per patch, 4 k-pos (= 4 quads) each
    const int bp  = tid >> 1;           // 0..63
    const int bk4 = (tid & 1) * 4;
    const int* xp = x + (size_t)(mt * 64 + bp) * 500 + bk4;

    auto build_A = [&](int buf, int4 xv, bool valid) {
        char* A = smem + buf * STG + A_OFF;
#pragma unroll
        for (int pp = 0; pp < 4; pp++) {
            int q = bk4 + pp;
            uint4 v = {0, 0, 0, 0};
            if (valid) {
                int idx = (pp == 0) ? xv.x : (pp == 1) ? xv.y
                        : (pp == 2) ? xv.z : xv.w;
                v = eT[idx];
            }
            *(uint4*)(A + swz128(bp, q)) = v;
        }
    };
    auto load_B = [&](int c, int buf) {
        uint32_t d = sb + buf * STG + B_OFF + tid * 16;
        const unsigned char* g = g_B + (size_t)c * 32768 + nt * 8192 + tid * 16;
#pragma unroll
        for (int q = 0; q < 4; q++) cp_async16(d + q * 2048, g + q * 2048);
        cp_commit();
    };

    // ldmatrix lane-relative bases
    uint32_t arow[2], brow[2];
    int arx[2], brx[2];
    const int aq = lane >> 4;           // A quad select
    const int mat = lane >> 3;
    const int bq = mat & 1;             // B quad select
#pragma unroll
    for (int fm = 0; fm < 2; fm++) {
        int row = wm * 32 + fm * 16 + (lane & 15);
        arow[fm] = A_OFF + row * 128;
        arx[fm]  = row & 7;
    }
#pragma unroll
    for (int f2 = 0; f2 < 2; f2++) {
        int row = wn * 32 + f2 * 16 + (mat >> 1) * 8 + (lane & 7);
        brow[f2] = B_OFF + row * 128;
        brx[f2]  = row & 7;
    }

    __syncthreads();                    // emb table ready

    // ---- prologue: stages 0, 1 (chunks 0, 1 fully valid: k-pos <= 15) ----
    load_B(0, 0);
    load_B(1, 1);
    build_A(0, *(const int4*)xp, true);
    build_A(1, *(const int4*)(xp + 8), true);
    int4 xv = *(const int4*)(xp + 16);  // chunk 2 (always valid)

    for (int it = 0; it < NCHUNK; ++it) {
        if (it + 1 < NCHUNK) cp_wait<1>(); else cp_wait<0>();
        __syncthreads();                // stage(it) ready; slot (it+2)%3 free

        const int nb = it + 2;
        if (nb < NCHUNK) {
            const int slot = nb % 3;
            load_B(nb, slot);
            build_A(slot, xv, (nb * 8 + bk4) < 500);
            if (nb + 1 < NCHUNK && ((nb + 1) * 8 + bk4) < 500)
                xv = *(const int4*)(xp + (nb + 1) * 8);
        }

        const uint32_t stg = sb + (it % 3) * STG;
#pragma unroll
        for (int ks = 0; ks < 4; ks++) {
            uint32_t ah[2][4];
#pragma unroll
            for (int fm = 0; fm < 2; fm++)
                ldsm4(stg + arow[fm] + (((2 * ks + aq) ^ arx[fm]) << 4), ah[fm]);
#pragma unroll
            for (int f2 = 0; f2 < 2; f2++) {
                uint32_t bh[4];
                ldsm4(stg + brow[f2] + (((2 * ks + bq) ^ brx[f2]) << 4), bh);
#pragma unroll
                for (int fm = 0; fm < 2; fm++) {
#pragma unroll
                    for (int fb = 0; fb < 2; fb++)
                        mma16816(acc[fm][f2 * 2 + fb], ah[fm],
                                 bh[2 * fb], bh[2 * fb + 1]);
                }
            }
        }
    }

    // ---- epilogue: bias + GLU + relu + max over patches ----
    const int wbase = mt * 64 + wm * 32;
    const bool straddle = (wbase / 2000) != ((wbase + 31) / 2000);
#pragma unroll
    for (int fn = 0; fn < 4; fn++) {
        int j = nt * 32 + wn * 16 + fn * 4 + (lane & 3);
        float bb1 = b1[j], bb2 = b2[j];
        float h[2][2];
#pragma unroll
        for (int fm = 0; fm < 2; fm++) {
#pragma unroll
            for (int hf = 0; hf < 2; hf++) {
                float g1 = acc[fm][fn][hf * 2 + 0] + bb1;
                float g2 = acc[fm][fn][hf * 2 + 1] + bb2;
                h[fm][hf] = fmaxf(g1 * (1.f / (1.f + expf(-g2))), 0.f);
            }
        }
        if (!straddle) {
            float hm = fmaxf(fmaxf(h[0][0], h[0][1]), fmaxf(h[1][0], h[1][1]));
            hm = fmaxf(hm, __shfl_xor_sync(0xFFFFFFFFu, hm, 4));
            hm = fmaxf(hm, __shfl_xor_sync(0xFFFFFFFFu, hm, 8));
            hm = fmaxf(hm, __shfl_xor_sync(0xFFFFFFFFu, hm, 16));
            if ((lane >> 2) == 0)
                atomicMax(&g_m[(wbase / 2000) * 128 + j], __float_as_int(hm));
        } else {
#pragma unroll
            for (int fm = 0; fm < 2; fm++) {
#pragma unroll
                for (int hf = 0; hf < 2; hf++) {
                    int gp = wbase + fm * 16 + (lane >> 2) + hf * 8;
                    atomicMax(&g_m[(gp / 2000) * 128 + j],
                              __float_as_int(h[fm][hf]));
                }
            }
        }
    }
}

// ---------------------------------------------------------------------------
__global__ void fc_kernel(const float* __restrict__ fcW,
                          const float* __restrict__ fcb,
                          float* __restrict__ out) {
    int w    = threadIdx.x >> 5;
    int lane = threadIdx.x & 31;
    for (int pair = w; pair < BATCH * 2; pair += 8) {
        int b = pair >> 1;
        int j = pair & 1;
        float s = 0.f;
        for (int o = lane; o < 128; o += 32)
            s += __int_as_float(g_m[b * 128 + o]) * fcW[j * 128 + o];
#pragma unroll
        for (int off = 16; off; off >>= 1)
            s += __shfl_down_sync(0xFFFFFFFFu, s, off);
        if (lane == 0) out[b * 2 + j] = s + fcb[j];
    }
}

// ---------------------------------------------------------------------------
extern "C" void kernel_launch(void* const* d_in, const int* in_sizes, int n_in,
                              void* d_out, int out_size) {
    const int*   x   = (const int*)d_in[0];
    const float* emb = (const float*)d_in[1];
    const float* W1  = (const float*)d_in[2];
    const float* b1  = (const float*)d_in[3];
    const float* W2  = (const float*)d_in[4];
    const float* b2  = (const float*)d_in[5];
    const float* fcW = (const float*)d_in[6];
    const float* fcb = (const float*)d_in[7];
    float*       out = (float*)d_out;

    cudaFuncSetAttribute(malconv_kernel,
                         cudaFuncAttributeMaxDynamicSharedMemorySize, SMEM_TOTAL);

    pack_kernel<<<256, 256>>>(W1, W2);
    malconv_kernel<<<1000, 128, SMEM_TOTAL>>>(x, emb, b1, b2);
    fc_kernel<<<1, 256>>>(fcW, fcb, out);
}

// round 13
// speedup vs baseline: 1.3059x; 1.3059x over previous
#include <cuda_runtime.h>
#include <cuda_fp16.h>
#include <cstdint>

// ---------------------------------------------------------------------------
// MalConv via single-pass fp16 mma.sync (m16n8k16, f32 accumulate).
//   C[16000,256] = E[16000,4000] x W[4000,256], fp16 operands, fp32 accum.
//   Columns interleaved (g1_j, g2_j) so mma C-pairs = (g1, g2).
//   CTA: 64 patches x 128 cols, 4 warps (2m x 2n), warp tile 32x64.
//   Grid: 250 m-tiles x 2 n-tiles = 500;  2-stage ring, 4 CTAs/SM.
//   K: 63 chunks of 64 (zero-padded past 4000).
// ---------------------------------------------------------------------------

#define NCHUNK   63
#define BATCH    8

// stage layout: A 64p x 128B (8 KB) | B 128n x 128B (16 KB)
#define A_OFF    0
#define B_OFF    8192
#define STG      24576
// after 2 stages:
#define EMB_OFF  49152          // uint4[257] fp16x8 rows
#define SMEM_TOTAL 53264

__device__ __align__(16) unsigned char g_B[NCHUNK * 32768]; // [c][256n][128B]
__device__ int g_m[BATCH * 128];

// ---------------------------------------------------------------------------
// pack: grid (256 cols, 2 chunk-halves). Coalesced W row-segment staging in
// smem; swizzled fp16 writes. Block (0,0) also zeroes g_m.
__global__ void pack_kernel(const float* __restrict__ W1,
                            const float* __restrict__ W2) {
    __shared__ float sw[8][256];             // [ch][k - half*256]
    const int n    = blockIdx.x;             // 0..255
    const int half = blockIdx.y;             // 0..1
    const int tid  = threadIdx.x;
    const int j    = n >> 1;
    const float* Wsrc = (n & 1) ? W2 : W1;
    if (n == 0 && half == 0) {
        for (int i = tid; i < BATCH * 128; i += 256) g_m[i] = 0;
    }
    // stage k range [half*256, half*256+256) for all 8 channels
    for (int i = tid; i < 8 * 256; i += 256) {
        int ch = i >> 8, kl = i & 255;
        int k  = half * 256 + kl;
        sw[ch][kl] = (k < 500) ? Wsrc[j * 4000 + ch * 500 + k] : 0.f;
    }
    __syncthreads();
    const int c0 = half * 32;
    const int cN = (half == 0) ? 32 : (NCHUNK - 32);   // 32 or 31 chunks
    for (int idx = tid; idx < cN * 64; idx += 256) {
        int c  = c0 + (idx >> 6);
        int kk = idx & 63;
        int k  = c * 8 + (kk >> 3);
        int ch = kk & 7;
        float v = sw[ch][k - half * 256];
        int quad = kk >> 3;
        size_t addr = (size_t)c * 32768 + n * 128
                    + (((quad ^ (n & 7)) << 4) | ((kk & 7) * 2));
        *(__half*)(g_B + addr) = __float2half(v);
    }
}

// ---------------------------------------------------------------------------
__device__ __forceinline__ void cp_async16(uint32_t dst, const void* src) {
    asm volatile("cp.async.cg.shared.global [%0], [%1], 16;" :: "r"(dst), "l"(src));
}
__device__ __forceinline__ void cp_commit() { asm volatile("cp.async.commit_group;"); }
template <int N> __device__ __forceinline__ void cp_wait() {
    asm volatile("cp.async.wait_group %0;" :: "n"(N));
}
__device__ __forceinline__ void ldsm4(uint32_t a, uint32_t* r) {
    asm volatile("ldmatrix.sync.aligned.m8n8.x4.shared.b16 {%0,%1,%2,%3}, [%4];"
                 : "=r"(r[0]), "=r"(r[1]), "=r"(r[2]), "=r"(r[3]) : "r"(a));
}
__device__ __forceinline__ void mma16816(float* d, const uint32_t* a,
                                         uint32_t b0, uint32_t b1) {
    asm volatile(
        "mma.sync.aligned.m16n8k16.row.col.f32.f16.f16.f32 "
        "{%0,%1,%2,%3}, {%4,%5,%6,%7}, {%8,%9}, {%0,%1,%2,%3};"
        : "+f"(d[0]), "+f"(d[1]), "+f"(d[2]), "+f"(d[3])
        : "r"(a[0]), "r"(a[1]), "r"(a[2]), "r"(a[3]), "r"(b0), "r"(b1));
}
__device__ __forceinline__ uint32_t swz128(int row, int quad) {
    return row * 128 + (((quad ^ (row & 7)) << 4));
}

// ---------------------------------------------------------------------------
__global__ void __launch_bounds__(128, 4)
malconv_kernel(const int* __restrict__ x, const float* __restrict__ emb,
               const float* __restrict__ b1, const float* __restrict__ b2) {
    extern __shared__ __align__(16) char smem[];
    const uint32_t sb = (uint32_t)__cvta_generic_to_shared(smem);
    const int tid  = threadIdx.x;
    const int lane = tid & 31;
    const int wid  = tid >> 5;          // 0..3
    const int wm   = wid >> 1;          // 0..1  (m-warp)
    const int wn   = wid & 1;           // 0..1  (n-warp)
    const int mt   = blockIdx.x >> 1;   // 0..249
    const int nt   = blockIdx.x & 1;    // 0..1

    // fp16 embedding table: uint4[257] (8 channels = 16 B per row)
    uint4* eT = (uint4*)(smem + EMB_OFF);
    for (int i = tid; i < 257 * 8; i += 128)
        ((__half*)eT)[i] = __float2half(emb[i]);

    float acc[2][8][4];
#pragma unroll
    for (int a = 0; a < 2; a++)
#pragma unroll
        for (int b = 0; b < 8; b++)
#pragma unroll
            for (int q = 0; q < 4; q++) acc[a][b][q] = 0.f;

    // builder: 2 threads per patch, 4 k-pos (= 4 quads) each
    const int bp  = tid >> 1;           // 0..63
    const int bk4 = (tid & 1) * 4;
    const int* xp = x + (size_t)(mt * 64 + bp) * 500 + bk4;

    auto build_A = [&](int buf, int4 xv, bool valid) {
        char* A = smem + buf * STG + A_OFF;
#pragma unroll
        for (int pp = 0; pp < 4; pp++) {
            int q = bk4 + pp;
            uint4 v = {0, 0, 0, 0};
            if (valid) {
                int idx = (pp == 0) ? xv.x : (pp == 1) ? xv.y
                        : (pp == 2) ? xv.z : xv.w;
                v = eT[idx];
            }
            *(uint4*)(A + swz128(bp, q)) = v;
        }
    };
    auto load_B = [&](int c, int buf) {
        uint32_t d = sb + buf * STG + B_OFF + tid * 16;
        const unsigned char* g = g_B + (size_t)c * 32768 + nt * 16384 + tid * 16;
#pragma unroll
        for (int q = 0; q < 8; q++) cp_async16(d + q * 2048, g + q * 2048);
        cp_commit();
    };

    // ldmatrix lane-relative bases
    uint32_t arow[2], brow[4];
    int arx[2], brx[4];
    const int aq = lane >> 4;           // A quad select
    const int mat = lane >> 3;
    const int bq = mat & 1;             // B quad select
#pragma unroll
    for (int fm = 0; fm < 2; fm++) {
        int row = wm * 32 + fm * 16 + (lane & 15);
        arow[fm] = A_OFF + row * 128;
        arx[fm]  = row & 7;
    }
#pragma unroll
    for (int f2 = 0; f2 < 4; f2++) {
        int row = wn * 64 + f2 * 16 + (mat >> 1) * 8 + (lane & 7);
        brow[f2] = B_OFF + row * 128;
        brx[f2]  = row & 7;
    }

    __syncthreads();                    // emb table ready

    // ---- prologue: stage 0 ----
    load_B(0, 0);
    build_A(0, *(const int4*)xp, true);
    int4 xv = *(const int4*)(xp + 8);   // chunk 1 (always valid)

    for (int it = 0; it < NCHUNK; ++it) {
        const int s = it & 1;
        __syncthreads();                // stage 1-s free (prev compute done)
        if (it + 1 < NCHUNK) {
            load_B(it + 1, 1 - s);
            build_A(1 - s, xv, ((it + 1) * 8 + bk4) < 500);
            if (it + 2 < NCHUNK && ((it + 2) * 8 + bk4) < 500)
                xv = *(const int4*)(xp + (it + 2) * 8);
            cp_wait<1>();               // B(it) arrived
        } else {
            cp_wait<0>();
        }
        __syncthreads();                // stage s visible

        const uint32_t stg = sb + s * STG;
#pragma unroll
        for (int ks = 0; ks < 4; ks++) {
            uint32_t ah[2][4];
#pragma unroll
            for (int fm = 0; fm < 2; fm++)
                ldsm4(stg + arow[fm] + (((2 * ks + aq) ^ arx[fm]) << 4), ah[fm]);
#pragma unroll
            for (int f2 = 0; f2 < 4; f2++) {
                uint32_t bh[4];
                ldsm4(stg + brow[f2] + (((2 * ks + bq) ^ brx[f2]) << 4), bh);
#pragma unroll
                for (int fm = 0; fm < 2; fm++) {
#pragma unroll
                    for (int fb = 0; fb < 2; fb++)
                        mma16816(acc[fm][f2 * 2 + fb], ah[fm],
                                 bh[2 * fb], bh[2 * fb + 1]);
                }
            }
        }
    }

    // ---- epilogue: bias + GLU + relu + max over patches ----
    const int wbase = mt * 64 + wm * 32;
    const bool straddle = (wbase / 2000) != ((wbase + 31) / 2000);
#pragma unroll
    for (int fn = 0; fn < 8; fn++) {
        int j = nt * 64 + wn * 32 + fn * 4 + (lane & 3);
        float bb1 = b1[j], bb2 = b2[j];
        float h[2][2];
#pragma unroll
        for (int fm = 0; fm < 2; fm++) {
#pragma unroll
            for (int hf = 0; hf < 2; hf++) {
                float g1 = acc[fm][fn][hf * 2 + 0] + bb1;
                float g2 = acc[fm][fn][hf * 2 + 1] + bb2;
                h[fm][hf] = fmaxf(g1 * (1.f / (1.f + expf(-g2))), 0.f);
            }
        }
        if (!straddle) {
            float hm = fmaxf(fmaxf(h[0][0], h[0][1]), fmaxf(h[1][0], h[1][1]));
            hm = fmaxf(hm, __shfl_xor_sync(0xFFFFFFFFu, hm, 4));
            hm = fmaxf(hm, __shfl_xor_sync(0xFFFFFFFFu, hm, 8));
            hm = fmaxf(hm, __shfl_xor_sync(0xFFFFFFFFu, hm, 16));
            if ((lane >> 2) == 0)
                atomicMax(&g_m[(wbase / 2000) * 128 + j], __float_as_int(hm));
        } else {
#pragma unroll
            for (int fm = 0; fm < 2; fm++) {
#pragma unroll
                for (int hf = 0; hf < 2; hf++) {
                    int gp = wbase + fm * 16 + (lane >> 2) + hf * 8;
                    atomicMax(&g_m[(gp / 2000) * 128 + j],
                              __float_as_int(h[fm][hf]));
                }
            }
        }
    }
}

// ---------------------------------------------------------------------------
__global__ void fc_kernel(const float* __restrict__ fcW,
                          const float* __restrict__ fcb,
                          float* __restrict__ out) {
    int w    = threadIdx.x >> 5;
    int lane = threadIdx.x & 31;
    for (int pair = w; pair < BATCH * 2; pair += 8) {
        int b = pair >> 1;
        int j = pair & 1;
        float s = 0.f;
        for (int o = lane; o < 128; o += 32)
            s += __int_as_float(g_m[b * 128 + o]) * fcW[j * 128 + o];
#pragma unroll
        for (int off = 16; off; off >>= 1)
            s += __shfl_down_sync(0xFFFFFFFFu, s, off);
        if (lane == 0) out[b * 2 + j] = s + fcb[j];
    }
}

// ---------------------------------------------------------------------------
extern "C" void kernel_launch(void* const* d_in, const int* in_sizes, int n_in,
                              void* d_out, int out_size) {
    const int*   x   = (const int*)d_in[0];
    const float* emb = (const float*)d_in[1];
    const float* W1  = (const float*)d_in[2];
    const float* b1  = (const float*)d_in[3];
    const float* W2  = (const float*)d_in[4];
    const float* b2  = (const float*)d_in[5];
    const float* fcW = (const float*)d_in[6];
    const float* fcb = (const float*)d_in[7];
    float*       out = (float*)d_out;

    cudaFuncSetAttribute(malconv_kernel,
                         cudaFuncAttributeMaxDynamicSharedMemorySize, SMEM_TOTAL);

    pack_kernel<<<dim3(256, 2), 256>>>(W1, W2);
    malconv_kernel<<<500, 128, SMEM_TOTAL>>>(x, emb, b1, b2);
    fc_kernel<<<1, 256>>>(fcW, fcb, out);
}